// round 1
// baseline (speedup 1.0000x reference)
#include <cuda_runtime.h>

constexpr int N  = 128;   // problem dimension
constexpr int HS = 132;   // H row stride in floats (132 % 32 == 4 -> conflict-free f4)
constexpr int MAXIT = 8;

struct SM {
    float H[N * HS];      // 67584 B, inverse Hessian (row-major, padded)
    float g[N];           // current (committed) gradient
    float d[N];           // search direction; also reused as x / x_next staging
    float s[N];           // step
    float dg[N];          // delta gradient
    float Hy[N];          // H * dg
    float red[8];         // reduction scratch
};

__device__ __forceinline__ float warp_sum(float v) {
    #pragma unroll
    for (int o = 16; o > 0; o >>= 1) v += __shfl_xor_sync(0xffffffffu, v, o);
    return v;
}

// two simultaneous block reductions (128 threads = 4 warps), 2 barriers
__device__ __forceinline__ void block_sum2(float& a, float& b, float* red, int tid) {
    a = warp_sum(a); b = warp_sum(b);
    if ((tid & 31) == 0) { red[tid >> 5] = a; red[4 + (tid >> 5)] = b; }
    __syncthreads();
    a = red[0] + red[1] + red[2] + red[3];
    b = red[4] + red[5] + red[6] + red[7];
    __syncthreads();
}

__device__ __forceinline__ float block_sum1(float a, float* red, int tid) {
    a = warp_sum(a);
    if ((tid & 31) == 0) red[tid >> 5] = a;
    __syncthreads();
    float r = red[0] + red[1] + red[2] + red[3];
    __syncthreads();
    return r;
}

__global__ __launch_bounds__(128, 3)
void bfgs_kernel(const float* __restrict__ Hinit,
                 const float* __restrict__ Q,
                 const float* __restrict__ bvec,
                 const float* __restrict__ x0,
                 float* __restrict__ out)
{
    extern __shared__ char smraw[];
    SM& sm = *reinterpret_cast<SM*>(smraw);

    const int i = threadIdx.x;          // this thread owns row/element i
    const int p = blockIdx.x;           // problem index (flattened B*E)
    const float* bp = bvec + p * N;
    const float* xp = x0   + p * N;

    // ---- init H from input (identity in practice, but honor the input) ----
    {
        const float4* hin  = reinterpret_cast<const float4*>(Hinit + i * N);
        float4*       hrow = reinterpret_cast<float4*>(&sm.H[i * HS]);
        #pragma unroll
        for (int k = 0; k < N / 4; k++) hrow[k] = hin[k];
    }

    float x_i = xp[i];
    sm.d[i] = x_i;                       // stage x in the d slot for the matvec
    __syncthreads();

    // ---- g = Q x - b  (Q symmetric: read column i => coalesced) ----
    float g_i = -bp[i];
    #pragma unroll 16
    for (int k = 0; k < N; k++) g_i += Q[k * N + i] * sm.d[k];
    sm.g[i] = g_i;
    __syncthreads();

    // ---- d = -H g ----
    float d_i;
    {
        const float4* hrow = reinterpret_cast<const float4*>(&sm.H[i * HS]);
        const float4* gv   = reinterpret_cast<const float4*>(sm.g);
        float acc = 0.f;
        #pragma unroll
        for (int k = 0; k < N / 4; k++) {
            float4 h = hrow[k]; float4 v = gv[k];
            acc += h.x * v.x; acc += h.y * v.y; acc += h.z * v.z; acc += h.w * v.w;
        }
        d_i = -acc;
    }
    sm.d[i] = d_i;
    __syncthreads();

    bool mask = true;                    // "updating" flag (block-uniform)

    for (int it = 0; it < MAXIT; ++it) {
        // ---- qd = Q d  (column access), reduce g.d and d.Qd ----
        float qd = 0.f;
        #pragma unroll 16
        for (int k = 0; k < N; k++) qd += Q[k * N + i] * sm.d[k];
        float gd  = g_i * d_i;
        float dqd = d_i * qd;
        block_sum2(gd, dqd, sm.red, i);

        const float alpha = -gd / fmaxf(dqd, 1e-12f);
        const float s_i   = alpha * d_i;
        const float xn_i  = x_i + s_i;
        sm.s[i] = s_i;
        sm.d[i] = xn_i;                  // reuse d slot as x_next for next matvec
        __syncthreads();

        // ---- g_next = Q x_next - b;  dg = g_next - g  (explicit, like ref) ----
        float gn_i = -bp[i];
        #pragma unroll 16
        for (int k = 0; k < N; k++) gn_i += Q[k * N + i] * sm.d[k];
        const float dg_i = gn_i - g_i;
        sm.dg[i] = dg_i;
        const float sdg = block_sum1(s_i * dg_i, sm.red, i);

        // ---- Hy = H dg  (H symmetric => also y'H) ----
        float hy = 0.f;
        {
            const float4* hrow = reinterpret_cast<const float4*>(&sm.H[i * HS]);
            const float4* v    = reinterpret_cast<const float4*>(sm.dg);
            #pragma unroll
            for (int k = 0; k < N / 4; k++) {
                float4 h = hrow[k]; float4 u = v[k];
                hy += h.x * u.x; hy += h.y * u.y; hy += h.z * u.z; hy += h.w * u.w;
            }
        }
        sm.Hy[i] = hy;

        // ---- commit x,g with OLD mask; reduce ihdg and ||g_committed||^2 ----
        const float xc = mask ? xn_i : x_i;
        const float gc = mask ? gn_i : g_i;
        float ihdg = dg_i * hy;
        float err2 = gc * gc;
        block_sum2(ihdg, err2, sm.red, i);
        x_i = xc; g_i = gc;
        sm.g[i] = gc;

        // ---- BFGS update coefficients (sdg == 0 -> dH = 0, exactly as ref) ----
        const bool  nz  = (sdg != 0.0f);
        const float biv = nz ? 1.0f / sdg : 0.0f;
        const float c1  = nz ? (sdg + ihdg) * biv * biv : 0.0f;
        const float a_i = s_i * c1 - hy * biv;   // coeff of s[j]
        const float b_i = s_i * biv;             // coeff of Hy[j]
        __syncthreads();                         // sm.g commits visible

        // ---- H += a_i*s' - b_i*Hy'  fused with  d_next = -H_new * g ----
        {
            float4*       hrow = reinterpret_cast<float4*>(&sm.H[i * HS]);
            const float4* s4   = reinterpret_cast<const float4*>(sm.s);
            const float4* y4   = reinterpret_cast<const float4*>(sm.Hy);
            const float4* g4   = reinterpret_cast<const float4*>(sm.g);
            float acc = 0.f;
            #pragma unroll
            for (int k = 0; k < N / 4; k++) {
                float4 h = hrow[k];
                float4 sv = s4[k]; float4 yv = y4[k]; float4 gv = g4[k];
                h.x += a_i * sv.x - b_i * yv.x;
                h.y += a_i * sv.y - b_i * yv.y;
                h.z += a_i * sv.z - b_i * yv.z;
                h.w += a_i * sv.w - b_i * yv.w;
                hrow[k] = h;
                acc += h.x * gv.x; acc += h.y * gv.y;
                acc += h.z * gv.z; acc += h.w * gv.w;
            }
            d_i = -acc;
        }
        sm.d[i] = d_i;
        mask = mask && (err2 > 1e-12f);          // err > 1e-6  <=>  err^2 > 1e-12
        __syncthreads();
    }

    out[p * N + i] = x_i;
}

extern "C" void kernel_launch(void* const* d_in, const int* in_sizes, int n_in,
                              void* d_out, int out_size)
{
    const float* Hinit = (const float*)d_in[0];
    const float* Q     = (const float*)d_in[1];
    const float* bvec  = (const float*)d_in[2];
    const float* x0    = (const float*)d_in[3];
    float*       out   = (float*)d_out;

    const int nprob = out_size / N;              // B*E = 1024
    const int smem  = (int)sizeof(SM);           // ~70 KB dynamic

    cudaFuncSetAttribute(bfgs_kernel, cudaFuncAttributeMaxDynamicSharedMemorySize, smem);
    bfgs_kernel<<<nprob, N, smem>>>(Hinit, Q, bvec, x0, out);
}

// round 2
// speedup vs baseline: 1.0017x; 1.0017x over previous
#include <cuda_runtime.h>

constexpr int N  = 128;   // problem dimension
constexpr int HS = 132;   // H row stride in floats (132 % 32 == 4 -> conflict-free f4)
constexpr int MAXIT = 8;

struct SM {
    float H[N * HS];      // 67584 B, inverse Hessian (row-major, padded)
    float g[N];           // current (committed) gradient
    float d[N];           // search direction; also reused as x / x_next staging
    float s[N];           // step
    float dg[N];          // delta gradient
    float Hy[N];          // H * dg
    float red[8];         // reduction scratch
};

__device__ __forceinline__ float warp_sum(float v) {
    #pragma unroll
    for (int o = 16; o > 0; o >>= 1) v += __shfl_xor_sync(0xffffffffu, v, o);
    return v;
}

// two simultaneous block reductions (128 threads = 4 warps), 2 barriers
__device__ __forceinline__ void block_sum2(float& a, float& b, float* red, int tid) {
    a = warp_sum(a); b = warp_sum(b);
    if ((tid & 31) == 0) { red[tid >> 5] = a; red[4 + (tid >> 5)] = b; }
    __syncthreads();
    a = red[0] + red[1] + red[2] + red[3];
    b = red[4] + red[5] + red[6] + red[7];
    __syncthreads();
}

__device__ __forceinline__ float block_sum1(float a, float* red, int tid) {
    a = warp_sum(a);
    if ((tid & 31) == 0) red[tid >> 5] = a;
    __syncthreads();
    float r = red[0] + red[1] + red[2] + red[3];
    __syncthreads();
    return r;
}

__global__ __launch_bounds__(128, 3)
void bfgs_kernel(const float* __restrict__ Hinit,
                 const float* __restrict__ Q,
                 const float* __restrict__ bvec,
                 const float* __restrict__ x0,
                 float* __restrict__ out)
{
    extern __shared__ char smraw[];
    SM& sm = *reinterpret_cast<SM*>(smraw);

    const int i = threadIdx.x;          // this thread owns row/element i
    const int p = blockIdx.x;           // problem index (flattened B*E)
    const float* bp = bvec + p * N;
    const float* xp = x0   + p * N;

    // ---- init H from input (identity in practice, but honor the input) ----
    {
        const float4* hin  = reinterpret_cast<const float4*>(Hinit + i * N);
        float4*       hrow = reinterpret_cast<float4*>(&sm.H[i * HS]);
        #pragma unroll
        for (int k = 0; k < N / 4; k++) hrow[k] = hin[k];
    }

    float x_i = xp[i];
    sm.d[i] = x_i;                       // stage x in the d slot for the matvec
    __syncthreads();

    // ---- g = Q x - b  (Q symmetric: read column i => coalesced) ----
    float g_i = -bp[i];
    #pragma unroll 16
    for (int k = 0; k < N; k++) g_i += Q[k * N + i] * sm.d[k];
    sm.g[i] = g_i;
    __syncthreads();

    // ---- d = -H g ----
    float d_i;
    {
        const float4* hrow = reinterpret_cast<const float4*>(&sm.H[i * HS]);
        const float4* gv   = reinterpret_cast<const float4*>(sm.g);
        float acc = 0.f;
        #pragma unroll
        for (int k = 0; k < N / 4; k++) {
            float4 h = hrow[k]; float4 v = gv[k];
            acc += h.x * v.x; acc += h.y * v.y; acc += h.z * v.z; acc += h.w * v.w;
        }
        d_i = -acc;
    }
    sm.d[i] = d_i;
    __syncthreads();

    bool mask = true;                    // "updating" flag (block-uniform)

    for (int it = 0; it < MAXIT; ++it) {
        // ---- qd = Q d  (column access), reduce g.d and d.Qd ----
        float qd = 0.f;
        #pragma unroll 16
        for (int k = 0; k < N; k++) qd += Q[k * N + i] * sm.d[k];
        float gd  = g_i * d_i;
        float dqd = d_i * qd;
        block_sum2(gd, dqd, sm.red, i);

        const float alpha = -gd / fmaxf(dqd, 1e-12f);
        const float s_i   = alpha * d_i;
        const float xn_i  = x_i + s_i;
        sm.s[i] = s_i;
        sm.d[i] = xn_i;                  // reuse d slot as x_next for next matvec
        __syncthreads();

        // ---- g_next = Q x_next - b;  dg = g_next - g  (explicit, like ref) ----
        float gn_i = -bp[i];
        #pragma unroll 16
        for (int k = 0; k < N; k++) gn_i += Q[k * N + i] * sm.d[k];
        const float dg_i = gn_i - g_i;
        sm.dg[i] = dg_i;
        const float sdg = block_sum1(s_i * dg_i, sm.red, i);

        // ---- Hy = H dg  (H symmetric => also y'H) ----
        float hy = 0.f;
        {
            const float4* hrow = reinterpret_cast<const float4*>(&sm.H[i * HS]);
            const float4* v    = reinterpret_cast<const float4*>(sm.dg);
            #pragma unroll
            for (int k = 0; k < N / 4; k++) {
                float4 h = hrow[k]; float4 u = v[k];
                hy += h.x * u.x; hy += h.y * u.y; hy += h.z * u.z; hy += h.w * u.w;
            }
        }
        sm.Hy[i] = hy;

        // ---- commit x,g with OLD mask; reduce ihdg and ||g_committed||^2 ----
        const float xc = mask ? xn_i : x_i;
        const float gc = mask ? gn_i : g_i;
        float ihdg = dg_i * hy;
        float err2 = gc * gc;
        block_sum2(ihdg, err2, sm.red, i);
        x_i = xc; g_i = gc;
        sm.g[i] = gc;

        // ---- BFGS update coefficients (sdg == 0 -> dH = 0, exactly as ref) ----
        const bool  nz  = (sdg != 0.0f);
        const float biv = nz ? 1.0f / sdg : 0.0f;
        const float c1  = nz ? (sdg + ihdg) * biv * biv : 0.0f;
        const float a_i = s_i * c1 - hy * biv;   // coeff of s[j]
        const float b_i = s_i * biv;             // coeff of Hy[j]
        __syncthreads();                         // sm.g commits visible

        // ---- H += a_i*s' - b_i*Hy'  fused with  d_next = -H_new * g ----
        {
            float4*       hrow = reinterpret_cast<float4*>(&sm.H[i * HS]);
            const float4* s4   = reinterpret_cast<const float4*>(sm.s);
            const float4* y4   = reinterpret_cast<const float4*>(sm.Hy);
            const float4* g4   = reinterpret_cast<const float4*>(sm.g);
            float acc = 0.f;
            #pragma unroll
            for (int k = 0; k < N / 4; k++) {
                float4 h = hrow[k];
                float4 sv = s4[k]; float4 yv = y4[k]; float4 gv = g4[k];
                h.x += a_i * sv.x - b_i * yv.x;
                h.y += a_i * sv.y - b_i * yv.y;
                h.z += a_i * sv.z - b_i * yv.z;
                h.w += a_i * sv.w - b_i * yv.w;
                hrow[k] = h;
                acc += h.x * gv.x; acc += h.y * gv.y;
                acc += h.z * gv.z; acc += h.w * gv.w;
            }
            d_i = -acc;
        }
        sm.d[i] = d_i;
        mask = mask && (err2 > 1e-12f);          // err > 1e-6  <=>  err^2 > 1e-12
        __syncthreads();
    }

    out[p * N + i] = x_i;
}

extern "C" void kernel_launch(void* const* d_in, const int* in_sizes, int n_in,
                              void* d_out, int out_size)
{
    const float* Hinit = (const float*)d_in[0];
    const float* Q     = (const float*)d_in[1];
    const float* bvec  = (const float*)d_in[2];
    const float* x0    = (const float*)d_in[3];
    float*       out   = (float*)d_out;

    const int nprob = out_size / N;              // B*E = 1024
    const int smem  = (int)sizeof(SM);           // ~70 KB dynamic

    cudaFuncSetAttribute(bfgs_kernel, cudaFuncAttributeMaxDynamicSharedMemorySize, smem);
    bfgs_kernel<<<nprob, N, smem>>>(Hinit, Q, bvec, x0, out);
}

// round 4
// speedup vs baseline: 2.0718x; 2.0684x over previous
#include <cuda_runtime.h>

constexpr int N     = 128;   // problem dimension
constexpr int MAXIT = 8;

// Small shared scratch: vectors + partial-combine buffer. H lives in registers.
struct SM {
    float d [N];
    float g [N];
    float s [N];
    float dg[N];
    float Hy[N];
    float qp[2 * N];   // per-thread partial dots (row i, half h) at qp[h*128+i]
    float red[16];     // block reduction scratch (8 warps x 2 values)
};

__device__ __forceinline__ float warp_sum(float v) {
    #pragma unroll
    for (int o = 16; o > 0; o >>= 1) v += __shfl_xor_sync(0xffffffffu, v, o);
    return v;
}

// two simultaneous block reductions over 256 threads (8 warps), 2 barriers
__device__ __forceinline__ void block_sum2(float& a, float& b, float* red, int tid) {
    a = warp_sum(a); b = warp_sum(b);
    const int w = tid >> 5;
    if ((tid & 31) == 0) { red[w] = a; red[8 + w] = b; }
    __syncthreads();
    a = red[0] + red[1] + red[2] + red[3] + red[4] + red[5] + red[6] + red[7];
    b = red[8] + red[9] + red[10] + red[11] + red[12] + red[13] + red[14] + red[15];
    __syncthreads();
}

__global__ __launch_bounds__(256, 2)
void bfgs_kernel(const float* __restrict__ Hinit,
                 const float* __restrict__ Q,
                 const float* __restrict__ bvec,
                 const float* __restrict__ x0,
                 float* __restrict__ out)
{
    __shared__ SM sm;

    const int t     = threadIdx.x;
    const int i     = t & 127;        // row / vector element owned
    const int half  = t >> 7;         // which 64-column chunk of row i
    const int kbase = half * 64;
    const int p     = blockIdx.x;

    const float* bp = bvec + p * N;
    const float* qcol = Q + (size_t)kbase * N + i;   // Q[(kbase+k)*N + i] = qcol[k*N]

    // ---- H chunk -> registers (row i, cols [kbase, kbase+64)) ----
    float4 h[16];
    {
        const float4* hin = reinterpret_cast<const float4*>(Hinit + i * N + kbase);
        #pragma unroll
        for (int k = 0; k < 16; k++) h[k] = hin[k];
    }

    // ---- stage x0; compute g0 = Q x0 - b via split column dot ----
    if (half == 0) sm.d[i] = x0[p * N + i];
    __syncthreads();

    {
        float part = 0.f;
        #pragma unroll 16
        for (int k = 0; k < 64; k++) part += qcol[k * N] * sm.d[kbase + k];
        sm.qp[t] = part;
    }
    __syncthreads();

    float g_i = 0.f, x_i = 0.f, d_i = 0.f;
    if (half == 0) {
        g_i = sm.qp[i] + sm.qp[128 + i] - bp[i];
        x_i = sm.d[i];
        sm.g[i] = g_i;
    }
    __syncthreads();

    // ---- d0 = -H g0 (register H, split dot) ----
    {
        const float4* gv = reinterpret_cast<const float4*>(sm.g + kbase);
        float dp = 0.f;
        #pragma unroll
        for (int k = 0; k < 16; k++) {
            float4 v = gv[k];
            dp += h[k].x * v.x; dp += h[k].y * v.y;
            dp += h[k].z * v.z; dp += h[k].w * v.w;
        }
        sm.qp[t] = dp;
    }
    __syncthreads();
    if (half == 0) {
        d_i = -(sm.qp[i] + sm.qp[128 + i]);
        sm.d[i] = d_i;
    }
    __syncthreads();

    bool mask = true;   // block-uniform "updating" flag

    for (int it = 0; it < MAXIT; ++it) {
        // ---- qd = Q d (split columns) ----
        float qdp = 0.f;
        #pragma unroll 16
        for (int k = 0; k < 64; k++) {
            qdp += qcol[k * N] * sm.d[kbase + k];
        }
        sm.qp[t] = qdp;
        // g.d: per-element product, contributed ONLY by half-0 threads
        // (round-3 bug: a half-uniform partial counted 128x)
        float gdp  = (half == 0) ? g_i * d_i : 0.f;
        float dqdp = sm.d[i] * qdp;          // sum_t d_i * partial = d.Qd
        block_sum2(gdp, dqdp, sm.red, t);    // syncs make qp visible
        const float gd = gdp, dqd = dqdp;

        const float alpha = -gd / fmaxf(dqd, 1e-12f);
        const float sdg   = alpha * alpha * dqd;   // s.dg = a^2 d.Qd exactly

        float s_i = 0.f, gn_i = 0.f;
        if (half == 0) {
            const float qd_i = sm.qp[i] + sm.qp[128 + i];
            const float dg_i = alpha * qd_i;       // dg = a * Qd (quadratic)
            gn_i = g_i + dg_i;
            s_i  = alpha * d_i;
            sm.dg[i] = dg_i;
            sm.s[i]  = s_i;
        }
        __syncthreads();

        // ---- Hy = H dg (register H); commit x,g with OLD mask ----
        {
            const float4* yv = reinterpret_cast<const float4*>(sm.dg + kbase);
            float hp = 0.f;
            #pragma unroll
            for (int k = 0; k < 16; k++) {
                float4 v = yv[k];
                hp += h[k].x * v.x; hp += h[k].y * v.y;
                hp += h[k].z * v.z; hp += h[k].w * v.w;
            }
            sm.qp[t] = hp;
        }
        __syncthreads();

        float ihp = 0.f, e2p = 0.f;
        if (half == 0) {
            const float hy_i = sm.qp[i] + sm.qp[128 + i];
            sm.Hy[i] = hy_i;
            ihp = sm.dg[i] * hy_i;                 // -> ihdg
            const float gc = mask ? gn_i : g_i;    // commit with old mask
            const float xc = mask ? x_i + s_i : x_i;
            g_i = gc; x_i = xc;
            sm.g[i] = gc;
            e2p = gc * gc;                         // -> ||g||^2
        }
        block_sum2(ihp, e2p, sm.red, t);           // makes Hy, g visible too
        const float ihdg = ihp, err2 = e2p;

        // ---- BFGS coefficients (sdg == 0 -> dH = 0, as reference) ----
        const bool  nz  = (sdg != 0.0f);
        const float biv = nz ? 1.0f / sdg : 0.0f;
        const float c1  = nz ? (sdg + ihdg) * biv * biv : 0.0f;
        const float s_row  = sm.s[i];
        const float hy_row = sm.Hy[i];
        const float a_i = s_row * c1 - biv * hy_row;  // coeff of s[j]
        const float b_i = biv * s_row;                // coeff of Hy[j]

        // ---- H += a_i s' - b_i Hy' in registers, fused d_next = -H_new g ----
        {
            const float4* s4 = reinterpret_cast<const float4*>(sm.s  + kbase);
            const float4* y4 = reinterpret_cast<const float4*>(sm.Hy + kbase);
            const float4* g4 = reinterpret_cast<const float4*>(sm.g  + kbase);
            float dp = 0.f;
            #pragma unroll
            for (int k = 0; k < 16; k++) {
                float4 sv = s4[k], yv = y4[k], gv = g4[k];
                h[k].x += a_i * sv.x - b_i * yv.x;  dp += h[k].x * gv.x;
                h[k].y += a_i * sv.y - b_i * yv.y;  dp += h[k].y * gv.y;
                h[k].z += a_i * sv.z - b_i * yv.z;  dp += h[k].z * gv.z;
                h[k].w += a_i * sv.w - b_i * yv.w;  dp += h[k].w * gv.w;
            }
            sm.qp[t] = dp;
        }
        __syncthreads();
        if (half == 0) {
            d_i = -(sm.qp[i] + sm.qp[128 + i]);
            sm.d[i] = d_i;
        }
        mask = mask && (err2 > 1e-12f);   // err > 1e-6  <=>  err^2 > 1e-12
        __syncthreads();
    }

    if (half == 0) out[p * N + i] = x_i;
}

extern "C" void kernel_launch(void* const* d_in, const int* in_sizes, int n_in,
                              void* d_out, int out_size)
{
    const float* Hinit = (const float*)d_in[0];
    const float* Q     = (const float*)d_in[1];
    const float* bvec  = (const float*)d_in[2];
    const float* x0    = (const float*)d_in[3];
    float*       out   = (float*)d_out;

    const int nprob = out_size / N;   // B*E = 1024
    bfgs_kernel<<<nprob, 256>>>(Hinit, Q, bvec, x0, out);
}